// round 6
// baseline (speedup 1.0000x reference)
#include <cuda_runtime.h>

typedef unsigned long long ull;

#define NB 512
#define NS 1024
#define NL 64
#define NC 66
#define LN2 0.6931471805599453f

static __device__ __forceinline__ ull fma2_(ull a, ull b, ull c) {
    ull d; asm("fma.rn.f32x2 %0, %1, %2, %3;" : "=l"(d) : "l"(a), "l"(b), "l"(c)); return d;
}
static __device__ __forceinline__ ull add2_(ull a, ull b) {
    ull d; asm("add.rn.f32x2 %0, %1, %2;" : "=l"(d) : "l"(a), "l"(b)); return d;
}
static __device__ __forceinline__ ull pack2_(float lo, float hi) {
    ull d; asm("mov.b64 %0, {%1, %2};" : "=l"(d) : "f"(lo), "f"(hi)); return d;
}
static __device__ __forceinline__ float2 unpack2_(ull v) {
    float lo, hi; asm("mov.b64 {%0, %1}, %2;" : "=f"(lo), "=f"(hi) : "l"(v)); return make_float2(lo, hi);
}

__global__ void zero_out_kernel(float* out) { out[0] = 0.0f; }

__global__ void __launch_bounds__(128, 1)
crf_fwd_kernel(const float* __restrict__ pred,
               const int*   __restrict__ ref,
               const int*   __restrict__ seq_len,
               const float* __restrict__ trans,
               float*       __restrict__ out)
{
    __shared__ __align__(16) float qbuf[4][2][64];

    const int w = threadIdx.x >> 5;
    const int l = threadIdx.x & 31;
    const int b = (blockIdx.x << 2) + w;
    const int j0 = 2 * l, j1 = 2 * l + 1;
    const int L = seq_len[b];

    // E columns for states j0, j1: 128 regs
    ull e0[32], e1[32];
#pragma unroll
    for (int k = 0; k < 32; ++k) {
        e0[k] = pack2_(__expf(trans[(2 * k) * NC + j0]), __expf(trans[(2 * k + 1) * NC + j0]));
        e1[k] = pack2_(__expf(trans[(2 * k) * NC + j1]), __expf(trans[(2 * k + 1) * NC + j1]));
    }
    const float Te0 = __expf(trans[j0 * NC + 65]);
    const float Te1 = __expf(trans[j1 * NC + 65]);

    const float* pb = pred + (size_t)b * NS * NL;

    float q0 = __expf(pb[j0] + trans[64 * NC + j0]);
    float q1 = __expf(pb[j1] + trans[64 * NC + j1]);

    float v = q0 * Te0 + q1 * Te1;   // covers L == 1
    int ecap = 0, esum = 0;

    float* buf0 = qbuf[w][0];
    float* buf1 = qbuf[w][1];
    ((float2*)buf0)[l] = make_float2(q0, q1);

    // pred pipeline via rolling clamped pointers (float2 units)
    const float2* p2    = (const float2*)pb;
    const float2* pend  = p2 + (size_t)(L - 1) * (NL / 2);   // last row
    const float2* pr    = p2 + (size_t)min(1, L - 1) * (NL / 2);
    float2 r1 = pr[l];
    pr += NL / 2; if (pr > pend) pr = pend;
    float2 r2 = pr[l];
    float w0 = __expf(r1.x - 4.0f);
    float w1 = __expf(r1.y - 4.0f);
    r1 = r2;
    pr += NL / 2; if (pr > pend) pr = pend;
    r2 = pr[l];

    __syncwarp(0xFFFFFFFFu);

// one chain step: read RP (q_{t-1}), write WP (q_t). Branch-free body.
#define STEP(RP, WP, T)                                                        \
    {                                                                          \
        const ulonglong2* rp2 = (const ulonglong2*)(RP);                       \
        float mref = (RP)[0];                                                  \
        ull a0 = 0, a1 = 0, a2 = 0, a3 = 0;                                    \
        ull c0 = 0, c1 = 0, c2 = 0, c3 = 0;                                    \
        _Pragma("unroll")                                                      \
        for (int k = 0; k < 8; ++k) {                                          \
            ulonglong2 v0 = rp2[2 * k];                                        \
            ulonglong2 v1 = rp2[2 * k + 1];                                    \
            a0 = fma2_(v0.x, e0[4 * k + 0], a0);                               \
            c0 = fma2_(v0.x, e1[4 * k + 0], c0);                               \
            a1 = fma2_(v0.y, e0[4 * k + 1], a1);                               \
            c1 = fma2_(v0.y, e1[4 * k + 1], c1);                               \
            a2 = fma2_(v1.x, e0[4 * k + 2], a2);                               \
            c2 = fma2_(v1.x, e1[4 * k + 2], c2);                               \
            a3 = fma2_(v1.y, e0[4 * k + 3], a3);                               \
            c3 = fma2_(v1.y, e1[4 * k + 3], c3);                               \
        }                                                                      \
        float2 fa = unpack2_(add2_(add2_(a0, a1), add2_(a2, a3)));             \
        float2 fc = unpack2_(add2_(add2_(c0, c1), add2_(c2, c3)));             \
        /* branchless renorm: scale by 2^-exponent(q_{t-1}[0]) */              \
        int e = ((__float_as_int(mref) >> 23) & 0xFF) - 127;                   \
        e = max(-100, min(100, e));                                            \
        float sc = __int_as_float((unsigned)(127 - e) << 23);                  \
        float sw0 = w0 * sc, sw1 = w1 * sc;                                    \
        float d0 = (fa.x + fa.y) * sw0;                                        \
        float d1 = (fc.x + fc.y) * sw1;                                        \
        esum += e;                                                             \
        /* branchless terminal capture */                                      \
        bool cap = ((T) == L);                                                 \
        float vc = d0 * Te0 + d1 * Te1;                                        \
        v    = cap ? vc   : v;                                                 \
        ecap = cap ? esum : ecap;                                              \
        ((float2*)(WP))[l] = make_float2(d0, d1);                              \
        /* pipeline rotate (off critical path) */                              \
        w0 = __expf(r1.x - 4.0f);                                              \
        w1 = __expf(r1.y - 4.0f);                                              \
        r1 = r2;                                                               \
        pr += NL / 2; if (pr > pend) pr = pend;                                \
        r2 = pr[l];                                                            \
        asm volatile("prefetch.global.L2 [%0];" :: "l"((const float*)pr + 256)); \
        __syncwarp(0xFFFFFFFFu);                                               \
    }

    int t = 2;
    for (; t + 1 <= L; t += 2) {
        STEP(buf0, buf1, t);
        STEP(buf1, buf0, t + 1);
    }
    if (t <= L) {
        STEP(buf0, buf1, t);
    }
#undef STEP

    // ---- real path score (lane-strided gather) ----
    float rsum = 0.0f;
    const int* rb = ref + (size_t)b * NS;
    for (int s = l; s < L; s += 32) {
        int r = rb[s];
        int p = (s == 0) ? 64 : rb[s - 1];
        rsum += pb[(size_t)s * NL + r] + trans[p * NC + r];
    }
    if (l == 0) rsum += trans[rb[L - 1] * NC + 65];

    // ---- in-warp reduction; one atomic per chain ----
#pragma unroll
    for (int o = 16; o; o >>= 1) {
        v    += __shfl_xor_sync(0xFFFFFFFFu, v, o);
        rsum += __shfl_xor_sync(0xFFFFFFFFu, rsum, o);
    }
    if (l == 0) {
        float contrib = 4.0f * (float)(L - 1) + LN2 * (float)ecap + __logf(v) - rsum;
        atomicAdd(out, contrib);
    }
}

extern "C" void kernel_launch(void* const* d_in, const int* in_sizes, int n_in,
                              void* d_out, int out_size)
{
    const float* pred  = (const float*)d_in[0];
    const int*   refp  = (const int*)d_in[1];
    const int*   seq   = (const int*)d_in[2];
    const float* trans = (const float*)d_in[3];
    float* outp = (float*)d_out;

    zero_out_kernel<<<1, 1>>>(outp);
    crf_fwd_kernel<<<NB / 4, 128>>>(pred, refp, seq, trans, outp);
}

// round 7
// speedup vs baseline: 1.0428x; 1.0428x over previous
#include <cuda_runtime.h>

typedef unsigned long long ull;

#define NB 512
#define NS 1024
#define NL 64
#define NC 66
#define LN2 0.6931471805599453f

static __device__ __forceinline__ ull fma2_(ull a, ull b, ull c) {
    ull d; asm("fma.rn.f32x2 %0, %1, %2, %3;" : "=l"(d) : "l"(a), "l"(b), "l"(c)); return d;
}
static __device__ __forceinline__ ull add2_(ull a, ull b) {
    ull d; asm("add.rn.f32x2 %0, %1, %2;" : "=l"(d) : "l"(a), "l"(b)); return d;
}
static __device__ __forceinline__ ull pack2_(float lo, float hi) {
    ull d; asm("mov.b64 %0, {%1, %2};" : "=l"(d) : "f"(lo), "f"(hi)); return d;
}
static __device__ __forceinline__ float2 unpack2_(ull v) {
    float lo, hi; asm("mov.b64 {%0, %1}, %2;" : "=f"(lo), "=f"(hi) : "l"(v)); return make_float2(lo, hi);
}

__global__ void zero_out_kernel(float* out) { out[0] = 0.0f; }

__global__ void __launch_bounds__(128, 1)
crf_fwd_kernel(const float* __restrict__ pred,
               const int*   __restrict__ ref,
               const int*   __restrict__ seq_len,
               const float* __restrict__ trans,
               float*       __restrict__ out)
{
    __shared__ __align__(16) float qbuf[4][2][64];

    const int w = threadIdx.x >> 5;
    const int l = threadIdx.x & 31;
    const int b = (blockIdx.x << 2) + w;
    const int j0 = 2 * l, j1 = 2 * l + 1;
    const int L = seq_len[b];

    // E columns for states j0, j1: 128 regs
    ull e0[32], e1[32];
#pragma unroll
    for (int k = 0; k < 32; ++k) {
        e0[k] = pack2_(__expf(trans[(2 * k) * NC + j0]), __expf(trans[(2 * k + 1) * NC + j0]));
        e1[k] = pack2_(__expf(trans[(2 * k) * NC + j1]), __expf(trans[(2 * k + 1) * NC + j1]));
    }
    const float Te0 = __expf(trans[j0 * NC + 65]);
    const float Te1 = __expf(trans[j1 * NC + 65]);

    const float* pb = pred + (size_t)b * NS * NL;
    const float2* p2 = (const float2*)pb;
    const int last = L - 1;

    // init: q1 = exp(pred[0] + T[start])
    float q0 = __expf(pb[j0] + trans[64 * NC + j0]);
    float q1 = __expf(pb[j1] + trans[64 * NC + j1]);

    float v = q0 * Te0 + q1 * Te1;   // covers L == 1
    int ecap = 0, esum = 0;

    float* buf0 = qbuf[w][0];
    float* buf1 = qbuf[w][1];
    ((float2*)buf0)[l] = make_float2(q0, q1);

    // renorm scale for step 2, precomputed from q_1[0] via shfl (no LDS on entry)
    float mref = __shfl_sync(0xFFFFFFFFu, q0, 0);
    int   e_nx = max(-100, min(100, ((__float_as_int(mref) >> 23) & 0xFF) - 127));
    float sc_nx = __int_as_float((unsigned)(127 - e_nx) << 23);

    // ---- pred pipeline, depth 4: at top of step t:
    //   wcur = exp(row[t-1]-4) ; r1=row[t], r2=row[t+1], r3=row[t+2]
    float2 r1 = p2[(size_t)min(1, last) * 32 + l];
    float2 r2 = p2[(size_t)min(2, last) * 32 + l];
    float2 r3 = p2[(size_t)min(3, last) * 32 + l];
    float wc0 = __expf(r1.x - 4.0f);
    float wc1 = __expf(r1.y - 4.0f);
    r1 = r2; r2 = r3;
    r3 = p2[(size_t)min(4, last) * 32 + l];

    __syncwarp(0xFFFFFFFFu);

    for (int t = 2; t <= L; ++t) {
        const float* rp = (t & 1) ? buf1 : buf0;
        float*       wp = (t & 1) ? buf0 : buf1;
        const ulonglong2* rp2 = (const ulonglong2*)rp;

        // current step's scale (precomputed last step)
        const int   e_c  = e_nx;
        const float sw0 = wc0 * sc_nx;
        const float sw1 = wc1 * sc_nx;

        // dual matvec: 16 LDS.128 + 64 FFMA2, 8 accumulators
        ull a0 = 0, a1 = 0, a2 = 0, a3 = 0;
        ull c0 = 0, c1 = 0, c2 = 0, c3 = 0;
#pragma unroll
        for (int k = 0; k < 8; ++k) {
            ulonglong2 v0 = rp2[2 * k];
            ulonglong2 v1 = rp2[2 * k + 1];
            a0 = fma2_(v0.x, e0[4 * k + 0], a0);
            c0 = fma2_(v0.x, e1[4 * k + 0], c0);
            a1 = fma2_(v0.y, e0[4 * k + 1], a1);
            c1 = fma2_(v0.y, e1[4 * k + 1], c1);
            a2 = fma2_(v1.x, e0[4 * k + 2], a2);
            c2 = fma2_(v1.x, e1[4 * k + 2], c2);
            a3 = fma2_(v1.y, e0[4 * k + 3], a3);
            c3 = fma2_(v1.y, e1[4 * k + 3], c3);
        }
        float2 fa = unpack2_(add2_(add2_(a0, a1), add2_(a2, a3)));
        float2 fc = unpack2_(add2_(add2_(c0, c1), add2_(c2, c3)));
        float d0 = (fa.x + fa.y) * sw0;
        float d1 = (fc.x + fc.y) * sw1;
        esum += e_c;

        ((float2*)wp)[l] = make_float2(d0, d1);

        // ---- everything below is off the critical recurrence ----
        // next step's renorm scale from this step's q_t[0]
        mref = __shfl_sync(0xFFFFFFFFu, d0, 0);
        e_nx = max(-100, min(100, ((__float_as_int(mref) >> 23) & 0xFF) - 127));
        sc_nx = __int_as_float((unsigned)(127 - e_nx) << 23);

        // branchless terminal capture
        bool cap = (t == L);
        float vc = d0 * Te0 + d1 * Te1;
        v    = cap ? vc   : v;
        ecap = cap ? esum : ecap;

        // pred pipeline rotate: exp of row[t] (for step t+1), load row[t+3]
        wc0 = __expf(r1.x - 4.0f);
        wc1 = __expf(r1.y - 4.0f);
        r1 = r2; r2 = r3;
        r3 = p2[(size_t)min(t + 3, last) * 32 + l];
        asm volatile("prefetch.global.L2 [%0];" :: "l"(p2 + (size_t)min(t + 11, last) * 32 + l));

        __syncwarp(0xFFFFFFFFu);
    }

    // ---- real path score (lane-strided gather) ----
    float rsum = 0.0f;
    const int* rb = ref + (size_t)b * NS;
    for (int s = l; s < L; s += 32) {
        int r = rb[s];
        int p = (s == 0) ? 64 : rb[s - 1];
        rsum += pb[(size_t)s * NL + r] + trans[p * NC + r];
    }
    if (l == 0) rsum += trans[rb[L - 1] * NC + 65];

    // ---- in-warp reduction; one atomic per chain ----
#pragma unroll
    for (int o = 16; o; o >>= 1) {
        v    += __shfl_xor_sync(0xFFFFFFFFu, v, o);
        rsum += __shfl_xor_sync(0xFFFFFFFFu, rsum, o);
    }
    if (l == 0) {
        float contrib = 4.0f * (float)(L - 1) + LN2 * (float)ecap + __logf(v) - rsum;
        atomicAdd(out, contrib);
    }
}

extern "C" void kernel_launch(void* const* d_in, const int* in_sizes, int n_in,
                              void* d_out, int out_size)
{
    const float* pred  = (const float*)d_in[0];
    const int*   refp  = (const int*)d_in[1];
    const int*   seq   = (const int*)d_in[2];
    const float* trans = (const float*)d_in[3];
    float* outp = (float*)d_out;

    zero_out_kernel<<<1, 1>>>(outp);
    crf_fwd_kernel<<<NB / 4, 128>>>(pred, refp, seq, trans, outp);
}